// round 2
// baseline (speedup 1.0000x reference)
#include <cuda_runtime.h>
#include <math.h>

#define NSEQ 80
#define SW 256
#define C 128
#define NH 8
#define DH 16
#define FF 512
#define NTOK (NSEQ*SW)          // 20480
#define TOKC (NTOK*C)           // 2621440

#define OUT_L 0
#define OUT_R TOKC
#define RAW_L (2*TOKC)
#define RAW_R (2*TOKC + NSEQ*SW*SW*NH)

// Scratch (device globals: allocation-free)
__device__ float g_k[2][TOKC];
__device__ float g_q[2][TOKC];
__device__ float g_v[2][TOKC];
__device__ float g_msg[2][TOKC];

// ---------------------------------------------------------------------------
// Kernel 1: per-head KQV projection.  x[16] @ W[16,48] -> split k,q,v
// ---------------------------------------------------------------------------
__global__ __launch_bounds__(256) void proj_kernel(
    const float* __restrict__ feat_l, const float* __restrict__ feat_r,
    const float* __restrict__ kqv_w)
{
    __shared__ float sW[16*48];
    int tid = threadIdx.x;
    for (int i = tid; i < 16*48; i += 256) sW[i] = kqv_w[i];
    __syncthreads();

    int side = blockIdx.y;
    const float* feat = side ? feat_r : feat_l;
    int rl = tid >> 3;
    int h  = tid & 7;
    int row = blockIdx.x * 32 + rl;

    float x[16];
    const float4* xp = (const float4*)(feat + (long)row*C + h*DH);
#pragma unroll
    for (int i = 0; i < 4; i++) {
        float4 t = xp[i];
        x[4*i+0]=t.x; x[4*i+1]=t.y; x[4*i+2]=t.z; x[4*i+3]=t.w;
    }
    float o[48];
#pragma unroll
    for (int j = 0; j < 48; j++) o[j] = 0.f;
#pragma unroll
    for (int i = 0; i < 16; i++) {
        float xi = x[i];
#pragma unroll
        for (int j = 0; j < 48; j++) o[j] = fmaf(xi, sW[i*48+j], o[j]);
    }
    int nn = row >> 8, ss = row & 255;
    long base = (((long)(nn*NH + h))*SW + ss)*DH;
    float* kp = g_k[side] + base;
    float* qp = g_q[side] + base;
    float* vp = g_v[side] + base;
#pragma unroll
    for (int d = 0; d < 16; d++) { kp[d]=o[d]; qp[d]=o[16+d]; vp[d]=o[32+d]; }
}

// ---------------------------------------------------------------------------
// Kernel 2: cross attention. block = (l-tile of 32, n, side). thread = (l,h).
// Pass 1: raw = q.k + prev  (write raw, track max). Pass 2: softmax + AV.
// ---------------------------------------------------------------------------
__global__ __launch_bounds__(256) void attn_kernel(
    const float* __restrict__ prev_l, const float* __restrict__ prev_r,
    float* __restrict__ d_out)
{
    __shared__ float sKV[32*160];   // [s][h*20+d], pad avoids LDS.128 conflicts
    int tid  = threadIdx.x;
    int lt   = blockIdx.x;
    int nn   = blockIdx.y;
    int side = blockIdx.z;
    int l_loc = tid >> 3;
    int h     = tid & 7;
    int l = lt*32 + l_loc;

    const float* prev = side ? prev_r : prev_l;
    float* raw = d_out + (side ? RAW_R : RAW_L);
    const float* qb = g_q[side];
    const float* kb = g_k[side ^ 1];
    const float* vb = g_v[side ^ 1];

    float q[16];
    {
        const float4* qp = (const float4*)(qb + (((long)(nn*NH+h))*SW + l)*DH);
#pragma unroll
        for (int i = 0; i < 4; i++) {
            float4 t = qp[i];
            q[4*i+0]=t.x; q[4*i+1]=t.y; q[4*i+2]=t.z; q[4*i+3]=t.w;
        }
    }
    long pr_base = ((long)(nn*SW + l)*SW)*NH + h;

    // ---- pass 1: scores, raw write, running max ----
    float m = -1e30f;
    for (int sc = 0; sc < 8; sc++) {
        int s0 = sc*32;
        for (int j = tid; j < 1024; j += 256) {
            int hh = j >> 7, ss = (j >> 2) & 31, d4 = j & 3;
            float4 t = *(const float4*)(kb + (((long)(nn*NH+hh))*SW + s0+ss)*DH + d4*4);
            *(float4*)(&sKV[ss*160 + hh*20 + d4*4]) = t;
        }
        __syncthreads();
#pragma unroll 4
        for (int s = 0; s < 32; s++) {
            const float* kv = &sKV[s*160 + h*20];
            float dot = 0.f;
#pragma unroll
            for (int d = 0; d < 16; d++) dot = fmaf(q[d], kv[d], dot);
            long idx = pr_base + (long)(s0+s)*NH;
            float r = dot + prev[idx];
            raw[idx] = r;
            m = fmaxf(m, r);
        }
        __syncthreads();
    }
    m *= 0.25f;  // temp = 1/sqrt(16)

    // ---- pass 2: exp + AV accumulate ----
    float z = 0.f;
    float acc[16];
#pragma unroll
    for (int d = 0; d < 16; d++) acc[d] = 0.f;

    for (int sc = 0; sc < 8; sc++) {
        int s0 = sc*32;
        for (int j = tid; j < 1024; j += 256) {
            int hh = j >> 7, ss = (j >> 2) & 31, d4 = j & 3;
            float4 t = *(const float4*)(vb + (((long)(nn*NH+hh))*SW + s0+ss)*DH + d4*4);
            *(float4*)(&sKV[ss*160 + hh*20 + d4*4]) = t;
        }
        __syncthreads();
#pragma unroll 4
        for (int s = 0; s < 32; s++) {
            long idx = pr_base + (long)(s0+s)*NH;
            float r = raw[idx];                 // L2 hit (written by this block)
            float e = __expf(fmaf(r, 0.25f, -m));
            z += e;
            const float* vv = &sKV[s*160 + h*20];
#pragma unroll
            for (int d = 0; d < 16; d++) acc[d] = fmaf(e, vv[d], acc[d]);
        }
        __syncthreads();
    }
    float inv = 1.f / z;
    float* mp = g_msg[side] + ((long)(nn*SW + l))*C + h*DH;
#pragma unroll
    for (int d = 0; d < 16; d++) mp[d] = acc[d]*inv;
}

// ---------------------------------------------------------------------------
// Kernel 3: fused LN1 + FFN(GEMM 128->512, gelu, GEMM 512->128) + residual + LN2
// block = 32 token rows x side.
// ---------------------------------------------------------------------------
#define XPITCH 132
#define HPITCH 516

__global__ __launch_bounds__(256) void ffn_kernel(
    const float* __restrict__ feat_l, const float* __restrict__ feat_r,
    const float* __restrict__ w1, const float* __restrict__ b1,
    const float* __restrict__ w2, const float* __restrict__ b2,
    const float* __restrict__ lg1, const float* __restrict__ lb1,
    const float* __restrict__ lg2, const float* __restrict__ lb2,
    float* __restrict__ d_out)
{
    extern __shared__ float smem[];
    float* sX = smem;                 // 32 x 132
    float* sH = smem + 32*XPITCH;     // 32 x 516 (reused as out tile)
    int tid  = threadIdx.x;
    int side = blockIdx.y;
    const float* feat = side ? feat_r : feat_l;
    const float* msg  = g_msg[side];
    float* outp = d_out + (side ? OUT_R : OUT_L);
    int row0 = blockIdx.x * 32;
    int warp = tid >> 5, lane = tid & 31;

    // load feat + msg
    for (int j = tid; j < 1024; j += 256) {
        int r = j >> 5, c4 = j & 31;
        long gi = ((long)(row0+r))*C + c4*4;
        float4 a = *(const float4*)(feat + gi);
        float4 b = *(const float4*)(msg + gi);
        a.x += b.x; a.y += b.y; a.z += b.z; a.w += b.w;
        *(float4*)(&sX[r*XPITCH + c4*4]) = a;
    }
    __syncthreads();

    // LN1 in place (warp per 4 rows)
#pragma unroll
    for (int rr = 0; rr < 4; rr++) {
        int r = warp*4 + rr;
        float v0 = sX[r*XPITCH+lane],    v1 = sX[r*XPITCH+lane+32];
        float v2 = sX[r*XPITCH+lane+64], v3 = sX[r*XPITCH+lane+96];
        float sum = v0+v1+v2+v3;
        float sq  = v0*v0+v1*v1+v2*v2+v3*v3;
        for (int o = 16; o; o >>= 1) {
            sum += __shfl_xor_sync(~0u, sum, o);
            sq  += __shfl_xor_sync(~0u, sq,  o);
        }
        float mu = sum*(1.f/128.f);
        float rs = rsqrtf(sq*(1.f/128.f) - mu*mu + 1e-5f);
        sX[r*XPITCH+lane]    = (v0-mu)*rs*lg1[lane]    + lb1[lane];
        sX[r*XPITCH+lane+32] = (v1-mu)*rs*lg1[lane+32] + lb1[lane+32];
        sX[r*XPITCH+lane+64] = (v2-mu)*rs*lg1[lane+64] + lb1[lane+64];
        sX[r*XPITCH+lane+96] = (v3-mu)*rs*lg1[lane+96] + lb1[lane+96];
    }
    __syncthreads();

    // GEMM1: H[32,512] = X[32,128] @ W1[128,512]; thread tile 8x8
    {
        int cg = tid & 63, rg = tid >> 6;
        float acc[8][8];
#pragma unroll
        for (int i = 0; i < 8; i++)
#pragma unroll
            for (int j = 0; j < 8; j++) acc[i][j] = 0.f;
        const float* xr0 = sX + (rg*8)*XPITCH;
#pragma unroll 2
        for (int k = 0; k < 128; k++) {
            float xr[8];
#pragma unroll
            for (int i = 0; i < 8; i++) xr[i] = xr0[i*XPITCH + k];  // warp-uniform bcast
            float4 wa = *(const float4*)(w1 + (long)k*FF + cg*8);
            float4 wb = *(const float4*)(w1 + (long)k*FF + cg*8 + 4);
            float wv[8] = {wa.x,wa.y,wa.z,wa.w, wb.x,wb.y,wb.z,wb.w};
#pragma unroll
            for (int i = 0; i < 8; i++)
#pragma unroll
                for (int j = 0; j < 8; j++) acc[i][j] = fmaf(xr[i], wv[j], acc[i][j]);
        }
        // bias + exact gelu, store H tile
#pragma unroll
        for (int i = 0; i < 8; i++) {
#pragma unroll
            for (int j4 = 0; j4 < 2; j4++) {
                float4 o;
                float* po = (float*)&o;
#pragma unroll
                for (int j = 0; j < 4; j++) {
                    float hx = acc[i][j4*4+j] + b1[cg*8 + j4*4 + j];
                    po[j] = 0.5f*hx*(1.f + erff(hx*0.70710678118654752f));
                }
                *(float4*)(&sH[(rg*8+i)*HPITCH + cg*8 + j4*4]) = o;
            }
        }
    }
    __syncthreads();

    // GEMM2: O[32,128] = H[32,512] @ W2[512,128]; thread tile 4x4
    {
        int cg2 = tid & 31, rg2 = tid >> 5;
        float a2[4][4];
#pragma unroll
        for (int i = 0; i < 4; i++)
#pragma unroll
            for (int j = 0; j < 4; j++) a2[i][j] = 0.f;
        const float* hr0 = sH + (rg2*4)*HPITCH;
#pragma unroll 4
        for (int k = 0; k < 512; k++) {
            float hr[4];
#pragma unroll
            for (int i = 0; i < 4; i++) hr[i] = hr0[i*HPITCH + k];  // warp-uniform bcast
            float4 wv = *(const float4*)(w2 + (long)k*C + cg2*4);
#pragma unroll
            for (int i = 0; i < 4; i++) {
                a2[i][0] = fmaf(hr[i], wv.x, a2[i][0]);
                a2[i][1] = fmaf(hr[i], wv.y, a2[i][1]);
                a2[i][2] = fmaf(hr[i], wv.z, a2[i][2]);
                a2[i][3] = fmaf(hr[i], wv.w, a2[i][3]);
            }
        }
        __syncthreads();   // done reading sH; reuse as out tile
        float4 bv = *(const float4*)(b2 + cg2*4);
#pragma unroll
        for (int i = 0; i < 4; i++) {
            int r = rg2*4 + i;
            float4 xv = *(const float4*)(&sX[r*XPITCH + cg2*4]);
            float4 o;
            o.x = xv.x + a2[i][0] + bv.x;
            o.y = xv.y + a2[i][1] + bv.y;
            o.z = xv.z + a2[i][2] + bv.z;
            o.w = xv.w + a2[i][3] + bv.w;
            *(float4*)(&sH[r*XPITCH + cg2*4]) = o;
        }
    }
    __syncthreads();

    // LN2 + write out
#pragma unroll
    for (int rr = 0; rr < 4; rr++) {
        int r = warp*4 + rr;
        float v0 = sH[r*XPITCH+lane],    v1 = sH[r*XPITCH+lane+32];
        float v2 = sH[r*XPITCH+lane+64], v3 = sH[r*XPITCH+lane+96];
        float sum = v0+v1+v2+v3;
        float sq  = v0*v0+v1*v1+v2*v2+v3*v3;
        for (int o = 16; o; o >>= 1) {
            sum += __shfl_xor_sync(~0u, sum, o);
            sq  += __shfl_xor_sync(~0u, sq,  o);
        }
        float mu = sum*(1.f/128.f);
        float rs = rsqrtf(sq*(1.f/128.f) - mu*mu + 1e-5f);
        long go = ((long)(row0+r))*C;
        outp[go+lane]    = (v0-mu)*rs*lg2[lane]    + lb2[lane];
        outp[go+lane+32] = (v1-mu)*rs*lg2[lane+32] + lb2[lane+32];
        outp[go+lane+64] = (v2-mu)*rs*lg2[lane+64] + lb2[lane+64];
        outp[go+lane+96] = (v3-mu)*rs*lg2[lane+96] + lb2[lane+96];
    }
}

// ---------------------------------------------------------------------------
extern "C" void kernel_launch(void* const* d_in, const int* in_sizes, int n_in,
                              void* d_out, int out_size)
{
    const float* feat_l = (const float*)d_in[0];
    const float* feat_r = (const float*)d_in[1];
    const float* prev_l = (const float*)d_in[2];
    const float* prev_r = (const float*)d_in[3];
    const float* kqv_w  = (const float*)d_in[4];
    const float* ff_w1  = (const float*)d_in[5];
    const float* ff_b1  = (const float*)d_in[6];
    const float* ff_w2  = (const float*)d_in[7];
    const float* ff_b2  = (const float*)d_in[8];
    const float* ln1_g  = (const float*)d_in[9];
    const float* ln1_b  = (const float*)d_in[10];
    const float* ln2_g  = (const float*)d_in[11];
    const float* ln2_b  = (const float*)d_in[12];
    float* out = (float*)d_out;

    const int FFN_SMEM = (32*XPITCH + 32*HPITCH) * 4;   // 82944 B
    cudaFuncSetAttribute(ffn_kernel, cudaFuncAttributeMaxDynamicSharedMemorySize, FFN_SMEM);

    proj_kernel<<<dim3(NTOK/32, 2), 256>>>(feat_l, feat_r, kqv_w);
    attn_kernel<<<dim3(SW/32, NSEQ, 2), 256>>>(prev_l, prev_r, out);
    ffn_kernel<<<dim3(NTOK/32, 2), 256, FFN_SMEM>>>(
        feat_l, feat_r, ff_w1, ff_b1, ff_w2, ff_b2,
        ln1_g, ln1_b, ln2_g, ln2_b, out);
}